// round 10
// baseline (speedup 1.0000x reference)
#include <cuda_runtime.h>
#include <cuda_bf16.h>

// Problem dims (fixed by reference setup_inputs)
#define BB   64
#define NN   16
#define NP1  17
#define TT   128
#define HH   256

// Scratch (no allocations allowed -> __device__ globals)
__device__ float g_key[BB * NP1 * TT * HH];   // 35,651,584 floats
__device__ float g_val[BB * NP1 * TT * HH];
__device__ float g_qw [BB * TT * HH];         // 2,097,152 floats
__device__ float g_wqb[HH * HH];              // 65,536 floats

// ---------------- f32x2 packed-FMA helpers ----------------
__device__ __forceinline__ unsigned long long dup2(float a) {
    unsigned long long r;
    asm("mov.b64 %0, {%1, %1};" : "=l"(r) : "f"(a));
    return r;
}
__device__ __forceinline__ void ffma2(unsigned long long& c,
                                      unsigned long long a,
                                      unsigned long long b) {
    asm("fma.rn.f32x2 %0, %1, %2, %0;" : "+l"(c) : "l"(a), "l"(b));
}
__device__ __forceinline__ float2 unpack2(unsigned long long v) {
    float2 r;
    asm("mov.b64 {%0, %1}, %2;" : "=f"(r.x), "=f"(r.y) : "l"(v));
    return r;
}

// =====================================================================
// Generic 128x128 tile SGEMM, BK=16, 256 threads, 8x8 micro-tile, f32x2.
//   out[r][cB+j] = sum_k Xrow(r)[k] * Wel(k, cB+j)
// xmode: 0 = X rows plain; 1 = kv gather (X=node, X2=neigh); 2 = X transposed (A[r][k] = X[k][r])
// wtrans: 0 -> W[k][j] ; 1 -> W[j][k]  (i.e. out = X @ W^T)
// =====================================================================
__global__ __launch_bounds__(256) void gemm128(
    const float* __restrict__ X, const float* __restrict__ X2,
    const float* __restrict__ W, float* __restrict__ out,
    int xmode, int wtrans)
{
    __shared__ float As[128 * 17];   // [row][k], stride 17 (odd -> conflict-free bcast)
    __shared__ float Bs[16 * 132];   // [k][col], stride 132 (16B aligned)

    const int tid = threadIdx.x;
    const int ty = tid >> 4, tx = tid & 15;
    const int tm = ty * 8, tn = tx * 8;
    const int rowBase = blockIdx.y * 128;
    const int colBase = blockIdx.x * 128;

    unsigned long long acc[8][4];
#pragma unroll
    for (int i = 0; i < 8; i++)
#pragma unroll
        for (int p = 0; p < 4; p++) acc[i][p] = 0ull;

    for (int k0 = 0; k0 < HH; k0 += 16) {
        __syncthreads();
        // ---- load A tile ----
        if (xmode == 2) {
            // As[r][k] = X[k0+kk][rowBase+r]
#pragma unroll
            for (int l = 0; l < 2; l++) {
                int f4 = tid + l * 256;
                int kk = f4 >> 5;
                int r4 = (f4 & 31) << 2;
                float4 v = *(const float4*)(X + (size_t)(k0 + kk) * HH + rowBase + r4);
                As[(r4 + 0) * 17 + kk] = v.x;
                As[(r4 + 1) * 17 + kk] = v.y;
                As[(r4 + 2) * 17 + kk] = v.z;
                As[(r4 + 3) * 17 + kk] = v.w;
            }
        } else {
#pragma unroll
            for (int l = 0; l < 2; l++) {
                int f4 = tid + l * 256;
                int r = f4 >> 2;
                int kc = (f4 & 3) << 2;
                const float* src;
                if (xmode == 0) {
                    src = X + (size_t)(rowBase + r) * HH + k0 + kc;
                } else {
                    int rr = rowBase + r;
                    int b  = rr / (NP1 * TT);
                    int rem = rr - b * (NP1 * TT);
                    int n  = rem >> 7;
                    int t  = rem & (TT - 1);
                    if (n == 0)
                        src = X  + ((size_t)(b * TT + t)) * HH + k0 + kc;
                    else
                        src = X2 + ((size_t)((b * NN + (n - 1)) * TT + t)) * HH + k0 + kc;
                }
                float4 v = *(const float4*)src;
                As[r * 17 + kc + 0] = v.x;
                As[r * 17 + kc + 1] = v.y;
                As[r * 17 + kc + 2] = v.z;
                As[r * 17 + kc + 3] = v.w;
            }
        }
        // ---- load B tile ----
        if (!wtrans) {
#pragma unroll
            for (int l = 0; l < 2; l++) {
                int f4 = tid + l * 256;
                int kk = f4 >> 5;
                int j4 = (f4 & 31) << 2;
                float4 v = *(const float4*)(W + (size_t)(k0 + kk) * HH + colBase + j4);
                *(float4*)&Bs[kk * 132 + j4] = v;
            }
        } else {
#pragma unroll
            for (int l = 0; l < 2; l++) {
                int f4 = tid + l * 256;
                int j  = f4 >> 2;
                int kc = (f4 & 3) << 2;
                float4 v = *(const float4*)(W + (size_t)(colBase + j) * HH + k0 + kc);
                Bs[(kc + 0) * 132 + j] = v.x;
                Bs[(kc + 1) * 132 + j] = v.y;
                Bs[(kc + 2) * 132 + j] = v.z;
                Bs[(kc + 3) * 132 + j] = v.w;
            }
        }
        __syncthreads();
        // ---- micro-kernel ----
#pragma unroll
        for (int k = 0; k < 16; k++) {
            const ulonglong2* bp = (const ulonglong2*)(Bs + k * 132 + tn);
            ulonglong2 u0 = bp[0];
            ulonglong2 u1 = bp[1];
            unsigned long long b2[4] = {u0.x, u0.y, u1.x, u1.y};
            unsigned long long a2[8];
#pragma unroll
            for (int i = 0; i < 8; i++) a2[i] = dup2(As[(tm + i) * 17 + k]);
#pragma unroll
            for (int i = 0; i < 8; i++)
#pragma unroll
                for (int p = 0; p < 4; p++) ffma2(acc[i][p], a2[i], b2[p]);
        }
    }

    // ---- store ----
#pragma unroll
    for (int i = 0; i < 8; i++) {
        float2 p0 = unpack2(acc[i][0]);
        float2 p1 = unpack2(acc[i][1]);
        float2 p2 = unpack2(acc[i][2]);
        float2 p3 = unpack2(acc[i][3]);
        float4 v0 = make_float4(p0.x, p0.y, p1.x, p1.y);
        float4 v1 = make_float4(p2.x, p2.y, p3.x, p3.y);
        float* dst = out + (size_t)(rowBase + tm + i) * HH + colBase + tn;
        *(float4*)dst       = v0;
        *(float4*)(dst + 4) = v1;
    }
}

// =====================================================================
// Fused per-(b,n) attention: S = qW[b] @ key[b,n]^T + bias; softmax;
// write A; O = A @ value[b,n].  Grid: B*17 blocks, 256 threads.
// =====================================================================
#define SMEM_ATTN ((128 * 132 + 128 * 17 + 16 * 132) * 4)

__global__ __launch_bounds__(256) void attn_kernel(
    const float* __restrict__ qw, const float* __restrict__ key,
    const float* __restrict__ val, const float* __restrict__ bias,
    float* __restrict__ outO, float* __restrict__ outA, int writeA)
{
    extern __shared__ float sm[];
    float* sA = sm;                     // [128][132]
    float* sQ = sm + 128 * 132;         // [128][17]
    float* sK = sQ + 128 * 17;          // [16][132]
    float* sV = sQ;                     // alias of sQ region (phase 3)

    const int bn = blockIdx.x;
    const int b  = bn / NP1;
    const float* Qbase = qw  + (size_t)b  * TT * HH;
    const float* Kbase = key + (size_t)bn * TT * HH;
    const float* Vbase = val + (size_t)bn * TT * HH;

    const int tid = threadIdx.x;
    const int ty = tid >> 4, tx = tid & 15;
    const int tm = ty * 8, tn = tx * 8;

    unsigned long long acc[8][4];
#pragma unroll
    for (int i = 0; i < 8; i++)
#pragma unroll
        for (int p = 0; p < 4; p++) acc[i][p] = 0ull;

    // ---------------- Phase 1: S = Q K^T ----------------
    for (int k0 = 0; k0 < HH; k0 += 16) {
        __syncthreads();
#pragma unroll
        for (int l = 0; l < 2; l++) {            // Q tile [128 x 16]
            int f4 = tid + l * 256;
            int r = f4 >> 2;
            int kc = (f4 & 3) << 2;
            float4 v = *(const float4*)(Qbase + (size_t)r * HH + k0 + kc);
            sQ[r * 17 + kc + 0] = v.x;
            sQ[r * 17 + kc + 1] = v.y;
            sQ[r * 17 + kc + 2] = v.z;
            sQ[r * 17 + kc + 3] = v.w;
        }
#pragma unroll
        for (int l = 0; l < 2; l++) {            // K tile transposed -> [16 x 128]
            int f4 = tid + l * 256;
            int s = f4 >> 2;
            int kc = (f4 & 3) << 2;
            float4 v = *(const float4*)(Kbase + (size_t)s * HH + k0 + kc);
            sK[(kc + 0) * 132 + s] = v.x;
            sK[(kc + 1) * 132 + s] = v.y;
            sK[(kc + 2) * 132 + s] = v.z;
            sK[(kc + 3) * 132 + s] = v.w;
        }
        __syncthreads();
#pragma unroll
        for (int k = 0; k < 16; k++) {
            const ulonglong2* bp = (const ulonglong2*)(sK + k * 132 + tn);
            ulonglong2 u0 = bp[0];
            ulonglong2 u1 = bp[1];
            unsigned long long b2[4] = {u0.x, u0.y, u1.x, u1.y};
            unsigned long long a2[8];
#pragma unroll
            for (int i = 0; i < 8; i++) a2[i] = dup2(sQ[(tm + i) * 17 + k]);
#pragma unroll
            for (int i = 0; i < 8; i++)
#pragma unroll
                for (int p = 0; p < 4; p++) ffma2(acc[i][p], a2[i], b2[p]);
        }
    }

    // ---------------- Phase 2: bias + softmax (registers) ----------------
    float bj[8];
    {
        float4 b0 = *(const float4*)(bias + tn);
        float4 b1 = *(const float4*)(bias + tn + 4);
        bj[0] = b0.x; bj[1] = b0.y; bj[2] = b0.z; bj[3] = b0.w;
        bj[4] = b1.x; bj[5] = b1.y; bj[6] = b1.z; bj[7] = b1.w;
    }
    float c[8][8];
#pragma unroll
    for (int i = 0; i < 8; i++)
#pragma unroll
        for (int p = 0; p < 4; p++) {
            float2 v = unpack2(acc[i][p]);
            c[i][2 * p]     = v.x + bj[2 * p];
            c[i][2 * p + 1] = v.y + bj[2 * p + 1];
        }

#pragma unroll
    for (int i = 0; i < 8; i++) {
        float m = c[i][0];
#pragma unroll
        for (int j = 1; j < 8; j++) m = fmaxf(m, c[i][j]);
#pragma unroll
        for (int off = 1; off < 16; off <<= 1)
            m = fmaxf(m, __shfl_xor_sync(0xffffffffu, m, off, 16));
        float s = 0.f;
#pragma unroll
        for (int j = 0; j < 8; j++) { c[i][j] = __expf(c[i][j] - m); s += c[i][j]; }
#pragma unroll
        for (int off = 1; off < 16; off <<= 1)
            s += __shfl_xor_sync(0xffffffffu, s, off, 16);
        float inv = 1.0f / s;
#pragma unroll
        for (int j = 0; j < 8; j++) c[i][j] *= inv;
    }

    // write A and stage into SMEM for phase 3
#pragma unroll
    for (int i = 0; i < 8; i++) {
        int t = tm + i;
        float4 v0 = make_float4(c[i][0], c[i][1], c[i][2], c[i][3]);
        float4 v1 = make_float4(c[i][4], c[i][5], c[i][6], c[i][7]);
        if (writeA) {
            float* dst = outA + ((size_t)bn * TT + t) * TT + tn;
            *(float4*)dst       = v0;
            *(float4*)(dst + 4) = v1;
        }
        *(float4*)(sA + t * 132 + tn)     = v0;
        *(float4*)(sA + t * 132 + tn + 4) = v1;
    }
    __syncthreads();

    // ---------------- Phase 3: O = A @ V ----------------
    for (int hb = 0; hb < 2; hb++) {
#pragma unroll
        for (int i = 0; i < 8; i++)
#pragma unroll
            for (int p = 0; p < 4; p++) acc[i][p] = 0ull;

        for (int s0 = 0; s0 < TT; s0 += 16) {
            __syncthreads();
#pragma unroll
            for (int l = 0; l < 2; l++) {        // V tile [16 x 128]
                int f4 = tid + l * 256;
                int kk = f4 >> 5;
                int j4 = (f4 & 31) << 2;
                float4 v = *(const float4*)(Vbase + (size_t)(s0 + kk) * HH + hb * 128 + j4);
                *(float4*)(sV + kk * 132 + j4) = v;
            }
            __syncthreads();
#pragma unroll
            for (int k = 0; k < 16; k++) {
                const ulonglong2* bp = (const ulonglong2*)(sV + k * 132 + tn);
                ulonglong2 u0 = bp[0];
                ulonglong2 u1 = bp[1];
                unsigned long long b2[4] = {u0.x, u0.y, u1.x, u1.y};
                unsigned long long a2[8];
#pragma unroll
                for (int i = 0; i < 8; i++) a2[i] = dup2(sA[(tm + i) * 132 + s0 + k]);
#pragma unroll
                for (int i = 0; i < 8; i++)
#pragma unroll
                    for (int p = 0; p < 4; p++) ffma2(acc[i][p], a2[i], b2[p]);
            }
        }

#pragma unroll
        for (int i = 0; i < 8; i++) {
            float2 p0 = unpack2(acc[i][0]);
            float2 p1 = unpack2(acc[i][1]);
            float2 p2 = unpack2(acc[i][2]);
            float2 p3 = unpack2(acc[i][3]);
            float4 v0 = make_float4(p0.x, p0.y, p1.x, p1.y);
            float4 v1 = make_float4(p2.x, p2.y, p3.x, p3.y);
            float* dst = outO + (size_t)bn * TT * HH + (size_t)(tm + i) * HH + hb * 128 + tn;
            *(float4*)dst       = v0;
            *(float4*)(dst + 4) = v1;
        }
    }
}

// =====================================================================
// Host launcher
// =====================================================================
extern "C" void kernel_launch(void* const* d_in, const int* in_sizes, int n_in,
                              void* d_out, int out_size)
{
    const float* node = nullptr;
    const float* neigh = nullptr;
    const float* bias = nullptr;
    const float* Ws[4] = {nullptr, nullptr, nullptr, nullptr};
    int wc = 0;
    for (int i = 0; i < n_in; i++) {
        int s = in_sizes[i];
        if      (s == BB * TT * HH)            node  = (const float*)d_in[i];
        else if (s == BB * NN * TT * HH)       neigh = (const float*)d_in[i];
        else if (s == TT)                      bias  = (const float*)d_in[i];
        else if (s == HH * HH && wc < 4)       Ws[wc++] = (const float*)d_in[i];
    }
    const float* Wq = Ws[0];
    const float* Wk = Ws[1];
    const float* Wv = Ws[2];
    const float* Wb = Ws[3];

    float *key, *val, *qw, *wqb;
    cudaGetSymbolAddress((void**)&key, g_key);
    cudaGetSymbolAddress((void**)&val, g_val);
    cudaGetSymbolAddress((void**)&qw,  g_qw);
    cudaGetSymbolAddress((void**)&wqb, g_wqb);

    // 1) Wqb = Wq^T @ Wb         (xmode=2: A transposed)
    gemm128<<<dim3(2, 2), 256>>>(Wq, nullptr, Wb, wqb, 2, 0);
    // 2) qW = node @ Wqb         (8192 x 256 x 256)
    gemm128<<<dim3(2, BB * TT / 128), 256>>>(node, nullptr, wqb, qw, 0, 0);
    // 3) key = kv @ Wk^T         (139264 x 256 x 256, gathered rows)
    gemm128<<<dim3(2, BB * NP1 * TT / 128), 256>>>(node, neigh, Wk, key, 1, 1);
    // 4) value = kv @ Wv^T
    gemm128<<<dim3(2, BB * NP1 * TT / 128), 256>>>(node, neigh, Wv, val, 1, 1);

    // 5) fused attention
    const int O_elems = BB * NP1 * TT * HH;   // 35,651,584
    const int A_elems = BB * NP1 * TT * TT;   // 17,825,792
    int writeA = (out_size >= O_elems + A_elems) ? 1 : 0;
    float* outO = (float*)d_out;
    float* outA = outO + O_elems;

    cudaFuncSetAttribute(attn_kernel, cudaFuncAttributeMaxDynamicSharedMemorySize, SMEM_ATTN);
    attn_kernel<<<BB * NP1, 256, SMEM_ATTN>>>(qw, key, val, bias, outO, outA, writeA);
}

// round 11
// speedup vs baseline: 1.2230x; 1.2230x over previous
#include <cuda_runtime.h>
#include <cuda_bf16.h>

// Problem dims (fixed by reference setup_inputs)
#define BB   64
#define NN   16
#define NP1  17
#define TT   128
#define HH   256

// Scratch (no allocations allowed -> __device__ globals)
__device__ float g_key[BB * NP1 * TT * HH];
__device__ float g_val[BB * NP1 * TT * HH];
__device__ float g_qw [BB * TT * HH];
__device__ float g_wqb[HH * HH];

// ---------------- f32x2 packed-FMA helpers ----------------
__device__ __forceinline__ unsigned long long dup2(float a) {
    unsigned long long r;
    asm("mov.b64 %0, {%1, %1};" : "=l"(r) : "f"(a));
    return r;
}
__device__ __forceinline__ void ffma2(unsigned long long& c,
                                      unsigned long long a,
                                      unsigned long long b) {
    asm("fma.rn.f32x2 %0, %1, %2, %0;" : "+l"(c) : "l"(a), "l"(b));
}
__device__ __forceinline__ float2 unpack2(unsigned long long v) {
    float2 r;
    asm("mov.b64 {%0, %1}, %2;" : "=f"(r.x), "=f"(r.y) : "l"(v));
    return r;
}

// =====================================================================
// 128x128 tile SGEMM, BK=16, 256 threads, 8x8 micro-tile, f32x2.
// Double-buffered SMEM, A stored as pre-duplicated (a,a) 8B pairs.
// xmode: 0 plain rows; 1 kv gather (X=node, X2=neigh); 2 X transposed
// wtrans: 0 -> W[k][j]; 1 -> W[j][k]  (out = X @ W^T)
// =====================================================================
#define GEMM_AS_ULL (128 * 17)
#define GEMM_BS_F   (16 * 132)
#define GEMM_SMEM   (2 * GEMM_AS_ULL * 8 + 2 * GEMM_BS_F * 4)   // 51,712 B

__global__ __launch_bounds__(256, 2) void gemm128(
    const float* __restrict__ X, const float* __restrict__ X2,
    const float* __restrict__ W, float* __restrict__ out,
    int xmode, int wtrans)
{
    extern __shared__ char smraw[];
    unsigned long long* AsD = (unsigned long long*)smraw;          // [2][128*17]
    float* Bs = (float*)(smraw + 2 * GEMM_AS_ULL * 8);             // [2][16*132]

    const int tid = threadIdx.x;
    const int ty = tid >> 4, tx = tid & 15;
    const int tm = ty * 8, tn = tx * 8;
    const int rowBase = blockIdx.y * 128;
    const int colBase = blockIdx.x * 128;

    // ---- A loader setup (modes 0/1: row base pointers are k-invariant) ----
    const int rA  = tid >> 2;
    const int kcA = (tid & 3) << 2;
    const float* aPtr0 = nullptr;
    const float* aPtr1 = nullptr;
    if (xmode != 2) {
#pragma unroll
        for (int l = 0; l < 2; l++) {
            int rr = rowBase + rA + l * 64;
            const float* p;
            if (xmode == 0) {
                p = X + (size_t)rr * HH;
            } else {
                int b = rr / (NP1 * TT);
                int rem = rr - b * (NP1 * TT);
                int n = rem >> 7, t = rem & (TT - 1);
                p = (n == 0) ? X  + (size_t)(b * TT + t) * HH
                             : X2 + (size_t)((b * NN + (n - 1)) * TT + t) * HH;
            }
            if (l == 0) aPtr0 = p + kcA; else aPtr1 = p + kcA;
        }
    }
    // ---- B loader setup ----
    const int kkB = tid >> 5;             // wtrans=0
    const int j4B = (tid & 31) << 2;
    const int jB  = tid >> 2;             // wtrans=1
    const int kcB = (tid & 3) << 2;
    // ---- xmode==2 A loader indices ----
    const int kkA2 = tid >> 5;
    const int r4A2 = (tid & 31) << 2;

    float4 a0, a1, b0, b1;

    auto loadAB = [&](int k0) {
        if (xmode == 2) {
            a0 = *(const float4*)(X + (size_t)(k0 + kkA2) * HH + rowBase + r4A2);
            a1 = *(const float4*)(X + (size_t)(k0 + kkA2 + 8) * HH + rowBase + r4A2);
        } else {
            a0 = *(const float4*)(aPtr0 + k0);
            a1 = *(const float4*)(aPtr1 + k0);
        }
        if (!wtrans) {
            b0 = *(const float4*)(W + (size_t)(k0 + kkB) * HH + colBase + j4B);
            b1 = *(const float4*)(W + (size_t)(k0 + kkB + 8) * HH + colBase + j4B);
        } else {
            b0 = *(const float4*)(W + (size_t)(colBase + jB) * HH + k0 + kcB);
            b1 = *(const float4*)(W + (size_t)(colBase + jB + 64) * HH + k0 + kcB);
        }
    };
    auto storeAB = [&](int buf) {
        unsigned long long* A = AsD + buf * GEMM_AS_ULL;
        float* B = Bs + buf * GEMM_BS_F;
        if (xmode == 2) {
            A[(r4A2 + 0) * 17 + kkA2] = dup2(a0.x);
            A[(r4A2 + 1) * 17 + kkA2] = dup2(a0.y);
            A[(r4A2 + 2) * 17 + kkA2] = dup2(a0.z);
            A[(r4A2 + 3) * 17 + kkA2] = dup2(a0.w);
            A[(r4A2 + 0) * 17 + kkA2 + 8] = dup2(a1.x);
            A[(r4A2 + 1) * 17 + kkA2 + 8] = dup2(a1.y);
            A[(r4A2 + 2) * 17 + kkA2 + 8] = dup2(a1.z);
            A[(r4A2 + 3) * 17 + kkA2 + 8] = dup2(a1.w);
        } else {
            A[(rA)      * 17 + kcA + 0] = dup2(a0.x);
            A[(rA)      * 17 + kcA + 1] = dup2(a0.y);
            A[(rA)      * 17 + kcA + 2] = dup2(a0.z);
            A[(rA)      * 17 + kcA + 3] = dup2(a0.w);
            A[(rA + 64) * 17 + kcA + 0] = dup2(a1.x);
            A[(rA + 64) * 17 + kcA + 1] = dup2(a1.y);
            A[(rA + 64) * 17 + kcA + 2] = dup2(a1.z);
            A[(rA + 64) * 17 + kcA + 3] = dup2(a1.w);
        }
        if (!wtrans) {
            *(float4*)&B[kkB * 132 + j4B]       = b0;
            *(float4*)&B[(kkB + 8) * 132 + j4B] = b1;
        } else {
            B[(kcB + 0) * 132 + jB] = b0.x;
            B[(kcB + 1) * 132 + jB] = b0.y;
            B[(kcB + 2) * 132 + jB] = b0.z;
            B[(kcB + 3) * 132 + jB] = b0.w;
            B[(kcB + 0) * 132 + jB + 64] = b1.x;
            B[(kcB + 1) * 132 + jB + 64] = b1.y;
            B[(kcB + 2) * 132 + jB + 64] = b1.z;
            B[(kcB + 3) * 132 + jB + 64] = b1.w;
        }
    };

    unsigned long long acc[8][4];
#pragma unroll
    for (int i = 0; i < 8; i++)
#pragma unroll
        for (int p = 0; p < 4; p++) acc[i][p] = 0ull;

    loadAB(0);
    storeAB(0);
    __syncthreads();

#pragma unroll 1
    for (int it = 0; it < 16; ++it) {
        const int cur = it & 1;
        if (it < 15) loadAB((it + 1) * 16);
        const unsigned long long* A = AsD + cur * GEMM_AS_ULL;
        const float* B = Bs + cur * GEMM_BS_F;
#pragma unroll
        for (int k = 0; k < 16; k++) {
            ulonglong2 u0 = *(const ulonglong2*)(B + k * 132 + tn);
            ulonglong2 u1 = *(const ulonglong2*)(B + k * 132 + tn + 4);
            unsigned long long b2[4] = {u0.x, u0.y, u1.x, u1.y};
            unsigned long long a2[8];
#pragma unroll
            for (int i = 0; i < 8; i++) a2[i] = A[(tm + i) * 17 + k];
#pragma unroll
            for (int i = 0; i < 8; i++)
#pragma unroll
                for (int p = 0; p < 4; p++) ffma2(acc[i][p], a2[i], b2[p]);
        }
        if (it < 15) { storeAB(cur ^ 1); __syncthreads(); }
    }

#pragma unroll
    for (int i = 0; i < 8; i++) {
        float2 p0 = unpack2(acc[i][0]);
        float2 p1 = unpack2(acc[i][1]);
        float2 p2 = unpack2(acc[i][2]);
        float2 p3 = unpack2(acc[i][3]);
        float4 v0 = make_float4(p0.x, p0.y, p1.x, p1.y);
        float4 v1 = make_float4(p2.x, p2.y, p3.x, p3.y);
        float* dst = out + (size_t)(rowBase + tm + i) * HH + colBase + tn;
        *(float4*)dst       = v0;
        *(float4*)(dst + 4) = v1;
    }
}

// =====================================================================
// Fused per-(b,n) attention: S = qW[b] @ key[b,n]^T + bias; softmax;
// write A; O = A @ value[b,n].  Grid: B*17 blocks, 256 threads.
// Double-buffered K/V tiles; sA staged for phase 3.
// =====================================================================
#define ATTN_SA_F  (128 * 128)               // 65,536 B
#define ATTN_SQ_F  (128 * 17)                // per buffer
#define ATTN_SK_F  (16 * 132)                // per buffer (aliased with V)
#define SMEM_ATTN  (ATTN_SA_F * 4 + 2 * ATTN_SQ_F * 4 + 2 * ATTN_SK_F * 4)  // 99,840 B

__global__ __launch_bounds__(256, 2) void attn_kernel(
    const float* __restrict__ qw, const float* __restrict__ key,
    const float* __restrict__ val, const float* __restrict__ bias,
    float* __restrict__ outO, float* __restrict__ outA, int writeA)
{
    extern __shared__ float sm[];
    float* sA = sm;                                   // [128][128]
    float* sQ = sm + ATTN_SA_F;                       // [2][128*17]
    float* sK = sQ + 2 * ATTN_SQ_F;                   // [2][16*132]  (== sV)

    const int bn = blockIdx.x;
    const int b  = bn / NP1;
    const float* Qbase = qw  + (size_t)b  * TT * HH;
    const float* Kbase = key + (size_t)bn * TT * HH;
    const float* Vbase = val + (size_t)bn * TT * HH;

    const int tid = threadIdx.x;
    const int ty = tid >> 4, tx = tid & 15;
    const int tm = ty * 8, tn = tx * 8;

    // loader indices
    const int rL  = tid >> 2;            // Q/K loads: row/seq index
    const int kcL = (tid & 3) << 2;
    const int kkV = tid >> 5;            // V loads
    const int j4V = (tid & 31) << 2;

    float4 a0, a1, b0, b1;

    // ---------------- Phase 1: S = Q K^T (double-buffered) -------------
    auto loadQK = [&](int k0) {
        a0 = *(const float4*)(Qbase + (size_t)rL * HH + k0 + kcL);
        a1 = *(const float4*)(Qbase + (size_t)(rL + 64) * HH + k0 + kcL);
        b0 = *(const float4*)(Kbase + (size_t)rL * HH + k0 + kcL);
        b1 = *(const float4*)(Kbase + (size_t)(rL + 64) * HH + k0 + kcL);
    };
    auto storeQK = [&](int buf) {
        float* Q = sQ + buf * ATTN_SQ_F;
        float* K = sK + buf * ATTN_SK_F;
        Q[(rL)      * 17 + kcL + 0] = a0.x;
        Q[(rL)      * 17 + kcL + 1] = a0.y;
        Q[(rL)      * 17 + kcL + 2] = a0.z;
        Q[(rL)      * 17 + kcL + 3] = a0.w;
        Q[(rL + 64) * 17 + kcL + 0] = a1.x;
        Q[(rL + 64) * 17 + kcL + 1] = a1.y;
        Q[(rL + 64) * 17 + kcL + 2] = a1.z;
        Q[(rL + 64) * 17 + kcL + 3] = a1.w;
        K[(kcL + 0) * 132 + rL] = b0.x;
        K[(kcL + 1) * 132 + rL] = b0.y;
        K[(kcL + 2) * 132 + rL] = b0.z;
        K[(kcL + 3) * 132 + rL] = b0.w;
        K[(kcL + 0) * 132 + rL + 64] = b1.x;
        K[(kcL + 1) * 132 + rL + 64] = b1.y;
        K[(kcL + 2) * 132 + rL + 64] = b1.z;
        K[(kcL + 3) * 132 + rL + 64] = b1.w;
    };

    unsigned long long acc[8][4];
#pragma unroll
    for (int i = 0; i < 8; i++)
#pragma unroll
        for (int p = 0; p < 4; p++) acc[i][p] = 0ull;

    loadQK(0);
    storeQK(0);
    __syncthreads();

#pragma unroll 1
    for (int it = 0; it < 16; ++it) {
        const int cur = it & 1;
        if (it < 15) loadQK((it + 1) * 16);
        const float* Q = sQ + cur * ATTN_SQ_F;
        const float* K = sK + cur * ATTN_SK_F;
#pragma unroll
        for (int k = 0; k < 16; k++) {
            ulonglong2 u0 = *(const ulonglong2*)(K + k * 132 + tn);
            ulonglong2 u1 = *(const ulonglong2*)(K + k * 132 + tn + 4);
            unsigned long long b2[4] = {u0.x, u0.y, u1.x, u1.y};
            unsigned long long a2[8];
#pragma unroll
            for (int i = 0; i < 8; i++) a2[i] = dup2(Q[(tm + i) * 17 + k]);
#pragma unroll
            for (int i = 0; i < 8; i++)
#pragma unroll
                for (int p = 0; p < 4; p++) ffma2(acc[i][p], a2[i], b2[p]);
        }
        if (it < 15) { storeQK(cur ^ 1); __syncthreads(); }
    }
    __syncthreads();   // all threads done reading sK before V overwrites it

    // ---------------- Phase 2: bias + softmax (registers) --------------
    float bj[8];
    {
        float4 q0 = *(const float4*)(bias + tn);
        float4 q1 = *(const float4*)(bias + tn + 4);
        bj[0] = q0.x; bj[1] = q0.y; bj[2] = q0.z; bj[3] = q0.w;
        bj[4] = q1.x; bj[5] = q1.y; bj[6] = q1.z; bj[7] = q1.w;
    }
    float c[8][8];
#pragma unroll
    for (int i = 0; i < 8; i++)
#pragma unroll
        for (int p = 0; p < 4; p++) {
            float2 v = unpack2(acc[i][p]);
            c[i][2 * p]     = v.x + bj[2 * p];
            c[i][2 * p + 1] = v.y + bj[2 * p + 1];
        }

#pragma unroll
    for (int i = 0; i < 8; i++) {
        float m = c[i][0];
#pragma unroll
        for (int j = 1; j < 8; j++) m = fmaxf(m, c[i][j]);
#pragma unroll
        for (int off = 1; off < 16; off <<= 1)
            m = fmaxf(m, __shfl_xor_sync(0xffffffffu, m, off, 16));
        float s = 0.f;
#pragma unroll
        for (int j = 0; j < 8; j++) { c[i][j] = __expf(c[i][j] - m); s += c[i][j]; }
#pragma unroll
        for (int off = 1; off < 16; off <<= 1)
            s += __shfl_xor_sync(0xffffffffu, s, off, 16);
        float inv = 1.0f / s;
#pragma unroll
        for (int j = 0; j < 8; j++) c[i][j] *= inv;
    }

    // write A (global) and stage into sA for phase 3
#pragma unroll
    for (int i = 0; i < 8; i++) {
        int t = tm + i;
        float4 v0 = make_float4(c[i][0], c[i][1], c[i][2], c[i][3]);
        float4 v1 = make_float4(c[i][4], c[i][5], c[i][6], c[i][7]);
        if (writeA) {
            float* dst = outA + ((size_t)bn * TT + t) * TT + tn;
            *(float4*)dst       = v0;
            *(float4*)(dst + 4) = v1;
        }
        *(float4*)(sA + t * 128 + tn)     = v0;
        *(float4*)(sA + t * 128 + tn + 4) = v1;
    }

    // ---------------- Phase 3: O = A @ V (flattened, double-buffered) ---
    float* sV = sK;   // alias (sK region is free now)

    auto loadV = [&](int tt) {
        int hb = tt >> 3, sc = tt & 7;
        const float* p = Vbase + (size_t)(sc * 16 + kkV) * HH + hb * 128 + j4V;
        a0 = *(const float4*)p;
        a1 = *(const float4*)(p + 8 * HH);
    };
    auto storeV = [&](int buf) {
        float* V = sV + buf * ATTN_SK_F;
        *(float4*)&V[kkV * 132 + j4V]       = a0;
        *(float4*)&V[(kkV + 8) * 132 + j4V] = a1;
    };

    loadV(0);
    storeV(0);
    __syncthreads();   // covers sA stores + V tile 0

#pragma unroll 1
    for (int tt = 0; tt < 16; ++tt) {
        const int cur = tt & 1;
        const int hb = tt >> 3, sc = tt & 7;
        if (sc == 0) {
#pragma unroll
            for (int i = 0; i < 8; i++)
#pragma unroll
                for (int p = 0; p < 4; p++) acc[i][p] = 0ull;
        }
        if (tt < 15) loadV(tt + 1);
        const float* V = sV + cur * ATTN_SK_F;
        const int s0 = sc * 16;
#pragma unroll
        for (int k = 0; k < 16; k++) {
            ulonglong2 u0 = *(const ulonglong2*)(V + k * 132 + tn);
            ulonglong2 u1 = *(const ulonglong2*)(V + k * 132 + tn + 4);
            unsigned long long b2[4] = {u0.x, u0.y, u1.x, u1.y};
            unsigned long long a2[8];
#pragma unroll
            for (int i = 0; i < 8; i++) a2[i] = dup2(sA[(tm + i) * 128 + s0 + k]);
#pragma unroll
            for (int i = 0; i < 8; i++)
#pragma unroll
                for (int p = 0; p < 4; p++) ffma2(acc[i][p], a2[i], b2[p]);
        }
        if (tt < 15) { storeV(cur ^ 1); __syncthreads(); }
        if (sc == 7) {
#pragma unroll
            for (int i = 0; i < 8; i++) {
                float2 p0 = unpack2(acc[i][0]);
                float2 p1 = unpack2(acc[i][1]);
                float2 p2 = unpack2(acc[i][2]);
                float2 p3 = unpack2(acc[i][3]);
                float4 v0 = make_float4(p0.x, p0.y, p1.x, p1.y);
                float4 v1 = make_float4(p2.x, p2.y, p3.x, p3.y);
                float* dst = outO + (size_t)bn * TT * HH
                           + (size_t)(tm + i) * HH + hb * 128 + tn;
                *(float4*)dst       = v0;
                *(float4*)(dst + 4) = v1;
            }
        }
    }
}

// =====================================================================
// Host launcher
// =====================================================================
extern "C" void kernel_launch(void* const* d_in, const int* in_sizes, int n_in,
                              void* d_out, int out_size)
{
    const float* node = nullptr;
    const float* neigh = nullptr;
    const float* bias = nullptr;
    const float* Ws[4] = {nullptr, nullptr, nullptr, nullptr};
    int wc = 0;
    for (int i = 0; i < n_in; i++) {
        int s = in_sizes[i];
        if      (s == BB * TT * HH)            node  = (const float*)d_in[i];
        else if (s == BB * NN * TT * HH)       neigh = (const float*)d_in[i];
        else if (s == TT)                      bias  = (const float*)d_in[i];
        else if (s == HH * HH && wc < 4)       Ws[wc++] = (const float*)d_in[i];
    }
    const float* Wq = Ws[0];
    const float* Wk = Ws[1];
    const float* Wv = Ws[2];
    const float* Wb = Ws[3];

    float *key, *val, *qw, *wqb;
    cudaGetSymbolAddress((void**)&key, g_key);
    cudaGetSymbolAddress((void**)&val, g_val);
    cudaGetSymbolAddress((void**)&qw,  g_qw);
    cudaGetSymbolAddress((void**)&wqb, g_wqb);

    cudaFuncSetAttribute(gemm128, cudaFuncAttributeMaxDynamicSharedMemorySize, GEMM_SMEM);
    cudaFuncSetAttribute(attn_kernel, cudaFuncAttributeMaxDynamicSharedMemorySize, SMEM_ATTN);

    // 1) Wqb = Wq^T @ Wb
    gemm128<<<dim3(2, 2), 256, GEMM_SMEM>>>(Wq, nullptr, Wb, wqb, 2, 0);
    // 2) qW = node @ Wqb
    gemm128<<<dim3(2, BB * TT / 128), 256, GEMM_SMEM>>>(node, nullptr, wqb, qw, 0, 0);
    // 3) key = kv @ Wk^T  (gathered rows)
    gemm128<<<dim3(2, BB * NP1 * TT / 128), 256, GEMM_SMEM>>>(node, neigh, Wk, key, 1, 1);
    // 4) value = kv @ Wv^T
    gemm128<<<dim3(2, BB * NP1 * TT / 128), 256, GEMM_SMEM>>>(node, neigh, Wv, val, 1, 1);

    // 5) fused attention
    const int O_elems = BB * NP1 * TT * HH;   // 35,651,584
    const int A_elems = BB * NP1 * TT * TT;   // 17,825,792
    int writeA = (out_size >= O_elems + A_elems) ? 1 : 0;
    float* outO = (float*)d_out;
    float* outA = outO + O_elems;

    attn_kernel<<<BB * NP1, 256, SMEM_ATTN>>>(qw, key, val, bias, outO, outA, writeA);
}

// round 12
// speedup vs baseline: 1.2235x; 1.0004x over previous
#include <cuda_runtime.h>
#include <cuda_bf16.h>

// Problem dims (fixed by reference setup_inputs)
#define BB   64
#define NN   16
#define NP1  17
#define TT   128
#define HH   256

// Scratch (no allocations allowed -> __device__ globals)
__device__ float g_key[BB * NP1 * TT * HH];
__device__ float g_val[BB * NP1 * TT * HH];
__device__ float g_qw [BB * TT * HH];
__device__ float g_wqb[HH * HH];

// ---------------- f32x2 packed-FMA helpers ----------------
__device__ __forceinline__ unsigned long long dup2(float a) {
    unsigned long long r;
    asm("mov.b64 %0, {%1, %1};" : "=l"(r) : "f"(a));
    return r;
}
__device__ __forceinline__ void ffma2(unsigned long long& c,
                                      unsigned long long a,
                                      unsigned long long b) {
    asm("fma.rn.f32x2 %0, %1, %2, %0;" : "+l"(c) : "l"(a), "l"(b));
}
__device__ __forceinline__ float2 unpack2(unsigned long long v) {
    float2 r;
    asm("mov.b64 {%0, %1}, %2;" : "=f"(r.x), "=f"(r.y) : "l"(v));
    return r;
}

// =====================================================================
// 128x128 tile SGEMM, BK=16, 256 threads, 8x8 micro-tile, f32x2.
// Double-buffered SMEM, A stored as pre-duplicated (a,a) 8B pairs.
// xmode: 0 plain rows; 1 kv gather (X=node, X2=neigh); 2 X transposed
// wtrans: 0 -> W[k][j]; 1 -> W[j][k]  (out = X @ W^T)
// =====================================================================
#define GEMM_AS_ULL (128 * 17)
#define GEMM_BS_F   (16 * 132)
#define GEMM_SMEM   (2 * GEMM_AS_ULL * 8 + 2 * GEMM_BS_F * 4)   // 51,712 B

__global__ __launch_bounds__(256, 2) void gemm128(
    const float* __restrict__ X, const float* __restrict__ X2,
    const float* __restrict__ W, float* __restrict__ out,
    int xmode, int wtrans)
{
    extern __shared__ char smraw[];
    unsigned long long* AsD = (unsigned long long*)smraw;          // [2][128*17]
    float* Bs = (float*)(smraw + 2 * GEMM_AS_ULL * 8);             // [2][16*132]

    const int tid = threadIdx.x;
    const int ty = tid >> 4, tx = tid & 15;
    const int tm = ty * 8, tn = tx * 8;
    const int rowBase = blockIdx.y * 128;
    const int colBase = blockIdx.x * 128;

    // ---- A loader setup (modes 0/1: row base pointers are k-invariant) ----
    const int rA  = tid >> 2;
    const int kcA = (tid & 3) << 2;
    const float* aPtr0 = nullptr;
    const float* aPtr1 = nullptr;
    if (xmode != 2) {
#pragma unroll
        for (int l = 0; l < 2; l++) {
            int rr = rowBase + rA + l * 64;
            const float* p;
            if (xmode == 0) {
                p = X + (size_t)rr * HH;
            } else {
                int b = rr / (NP1 * TT);
                int rem = rr - b * (NP1 * TT);
                int n = rem >> 7, t = rem & (TT - 1);
                p = (n == 0) ? X  + (size_t)(b * TT + t) * HH
                             : X2 + (size_t)((b * NN + (n - 1)) * TT + t) * HH;
            }
            if (l == 0) aPtr0 = p + kcA; else aPtr1 = p + kcA;
        }
    }
    // ---- B loader setup ----
    const int kkB = tid >> 5;             // wtrans=0
    const int j4B = (tid & 31) << 2;
    const int jB  = tid >> 2;             // wtrans=1
    const int kcB = (tid & 3) << 2;
    // ---- xmode==2 A loader indices ----
    const int kkA2 = tid >> 5;
    const int r4A2 = (tid & 31) << 2;

    float4 a0, a1, b0, b1;

    auto loadAB = [&](int k0) {
        if (xmode == 2) {
            a0 = *(const float4*)(X + (size_t)(k0 + kkA2) * HH + rowBase + r4A2);
            a1 = *(const float4*)(X + (size_t)(k0 + kkA2 + 8) * HH + rowBase + r4A2);
        } else {
            a0 = *(const float4*)(aPtr0 + k0);
            a1 = *(const float4*)(aPtr1 + k0);
        }
        if (!wtrans) {
            b0 = *(const float4*)(W + (size_t)(k0 + kkB) * HH + colBase + j4B);
            b1 = *(const float4*)(W + (size_t)(k0 + kkB + 8) * HH + colBase + j4B);
        } else {
            b0 = *(const float4*)(W + (size_t)(colBase + jB) * HH + k0 + kcB);
            b1 = *(const float4*)(W + (size_t)(colBase + jB + 64) * HH + k0 + kcB);
        }
    };
    auto storeAB = [&](int buf) {
        unsigned long long* A = AsD + buf * GEMM_AS_ULL;
        float* B = Bs + buf * GEMM_BS_F;
        if (xmode == 2) {
            A[(r4A2 + 0) * 17 + kkA2] = dup2(a0.x);
            A[(r4A2 + 1) * 17 + kkA2] = dup2(a0.y);
            A[(r4A2 + 2) * 17 + kkA2] = dup2(a0.z);
            A[(r4A2 + 3) * 17 + kkA2] = dup2(a0.w);
            A[(r4A2 + 0) * 17 + kkA2 + 8] = dup2(a1.x);
            A[(r4A2 + 1) * 17 + kkA2 + 8] = dup2(a1.y);
            A[(r4A2 + 2) * 17 + kkA2 + 8] = dup2(a1.z);
            A[(r4A2 + 3) * 17 + kkA2 + 8] = dup2(a1.w);
        } else {
            A[(rA)      * 17 + kcA + 0] = dup2(a0.x);
            A[(rA)      * 17 + kcA + 1] = dup2(a0.y);
            A[(rA)      * 17 + kcA + 2] = dup2(a0.z);
            A[(rA)      * 17 + kcA + 3] = dup2(a0.w);
            A[(rA + 64) * 17 + kcA + 0] = dup2(a1.x);
            A[(rA + 64) * 17 + kcA + 1] = dup2(a1.y);
            A[(rA + 64) * 17 + kcA + 2] = dup2(a1.z);
            A[(rA + 64) * 17 + kcA + 3] = dup2(a1.w);
        }
        if (!wtrans) {
            *(float4*)&B[kkB * 132 + j4B]       = b0;
            *(float4*)&B[(kkB + 8) * 132 + j4B] = b1;
        } else {
            B[(kcB + 0) * 132 + jB] = b0.x;
            B[(kcB + 1) * 132 + jB] = b0.y;
            B[(kcB + 2) * 132 + jB] = b0.z;
            B[(kcB + 3) * 132 + jB] = b0.w;
            B[(kcB + 0) * 132 + jB + 64] = b1.x;
            B[(kcB + 1) * 132 + jB + 64] = b1.y;
            B[(kcB + 2) * 132 + jB + 64] = b1.z;
            B[(kcB + 3) * 132 + jB + 64] = b1.w;
        }
    };

    unsigned long long acc[8][4];
#pragma unroll
    for (int i = 0; i < 8; i++)
#pragma unroll
        for (int p = 0; p < 4; p++) acc[i][p] = 0ull;

    loadAB(0);
    storeAB(0);
    __syncthreads();

#pragma unroll 1
    for (int it = 0; it < 16; ++it) {
        const int cur = it & 1;
        if (it < 15) loadAB((it + 1) * 16);
        const unsigned long long* A = AsD + cur * GEMM_AS_ULL;
        const float* B = Bs + cur * GEMM_BS_F;
#pragma unroll
        for (int k = 0; k < 16; k++) {
            ulonglong2 u0 = *(const ulonglong2*)(B + k * 132 + tn);
            ulonglong2 u1 = *(const ulonglong2*)(B + k * 132 + tn + 4);
            unsigned long long b2[4] = {u0.x, u0.y, u1.x, u1.y};
            unsigned long long a2[8];
#pragma unroll
            for (int i = 0; i < 8; i++) a2[i] = A[(tm + i) * 17 + k];
#pragma unroll
            for (int i = 0; i < 8; i++)
#pragma unroll
                for (int p = 0; p < 4; p++) ffma2(acc[i][p], a2[i], b2[p]);
        }
        if (it < 15) { storeAB(cur ^ 1); __syncthreads(); }
    }

#pragma unroll
    for (int i = 0; i < 8; i++) {
        float2 p0 = unpack2(acc[i][0]);
        float2 p1 = unpack2(acc[i][1]);
        float2 p2 = unpack2(acc[i][2]);
        float2 p3 = unpack2(acc[i][3]);
        float4 v0 = make_float4(p0.x, p0.y, p1.x, p1.y);
        float4 v1 = make_float4(p2.x, p2.y, p3.x, p3.y);
        float* dst = out + (size_t)(rowBase + tm + i) * HH + colBase + tn;
        *(float4*)dst       = v0;
        *(float4*)(dst + 4) = v1;
    }
}

// =====================================================================
// Fused per-(b,n) attention: S = qW[b] @ key[b,n]^T + bias; softmax;
// write A; O = A @ value[b,n].  Grid: B*17 blocks, 256 threads.
// Double-buffered K/V tiles; sA staged for phase 3.
// =====================================================================
#define ATTN_SA_F  (128 * 128)               // 65,536 B
#define ATTN_SQ_F  (128 * 17)                // per buffer
#define ATTN_SK_F  (16 * 132)                // per buffer (aliased with V)
#define SMEM_ATTN  (ATTN_SA_F * 4 + 2 * ATTN_SQ_F * 4 + 2 * ATTN_SK_F * 4)  // 99,840 B

__global__ __launch_bounds__(256, 2) void attn_kernel(
    const float* __restrict__ qw, const float* __restrict__ key,
    const float* __restrict__ val, const float* __restrict__ bias,
    float* __restrict__ outO, float* __restrict__ outA, int writeA)
{
    extern __shared__ float sm[];
    float* sA = sm;                                   // [128][128]
    float* sQ = sm + ATTN_SA_F;                       // [2][128*17]
    float* sK = sQ + 2 * ATTN_SQ_F;                   // [2][16*132]  (== sV)

    const int bn = blockIdx.x;
    const int b  = bn / NP1;
    const float* Qbase = qw  + (size_t)b  * TT * HH;
    const float* Kbase = key + (size_t)bn * TT * HH;
    const float* Vbase = val + (size_t)bn * TT * HH;

    const int tid = threadIdx.x;
    const int ty = tid >> 4, tx = tid & 15;
    const int tm = ty * 8, tn = tx * 8;

    // loader indices
    const int rL  = tid >> 2;            // Q/K loads: row/seq index
    const int kcL = (tid & 3) << 2;
    const int kkV = tid >> 5;            // V loads
    const int j4V = (tid & 31) << 2;

    float4 a0, a1, b0, b1;

    // ---------------- Phase 1: S = Q K^T (double-buffered) -------------
    auto loadQK = [&](int k0) {
        a0 = *(const float4*)(Qbase + (size_t)rL * HH + k0 + kcL);
        a1 = *(const float4*)(Qbase + (size_t)(rL + 64) * HH + k0 + kcL);
        b0 = *(const float4*)(Kbase + (size_t)rL * HH + k0 + kcL);
        b1 = *(const float4*)(Kbase + (size_t)(rL + 64) * HH + k0 + kcL);
    };
    auto storeQK = [&](int buf) {
        float* Q = sQ + buf * ATTN_SQ_F;
        float* K = sK + buf * ATTN_SK_F;
        Q[(rL)      * 17 + kcL + 0] = a0.x;
        Q[(rL)      * 17 + kcL + 1] = a0.y;
        Q[(rL)      * 17 + kcL + 2] = a0.z;
        Q[(rL)      * 17 + kcL + 3] = a0.w;
        Q[(rL + 64) * 17 + kcL + 0] = a1.x;
        Q[(rL + 64) * 17 + kcL + 1] = a1.y;
        Q[(rL + 64) * 17 + kcL + 2] = a1.z;
        Q[(rL + 64) * 17 + kcL + 3] = a1.w;
        K[(kcL + 0) * 132 + rL] = b0.x;
        K[(kcL + 1) * 132 + rL] = b0.y;
        K[(kcL + 2) * 132 + rL] = b0.z;
        K[(kcL + 3) * 132 + rL] = b0.w;
        K[(kcL + 0) * 132 + rL + 64] = b1.x;
        K[(kcL + 1) * 132 + rL + 64] = b1.y;
        K[(kcL + 2) * 132 + rL + 64] = b1.z;
        K[(kcL + 3) * 132 + rL + 64] = b1.w;
    };

    unsigned long long acc[8][4];
#pragma unroll
    for (int i = 0; i < 8; i++)
#pragma unroll
        for (int p = 0; p < 4; p++) acc[i][p] = 0ull;

    loadQK(0);
    storeQK(0);
    __syncthreads();

#pragma unroll 1
    for (int it = 0; it < 16; ++it) {
        const int cur = it & 1;
        if (it < 15) loadQK((it + 1) * 16);
        const float* Q = sQ + cur * ATTN_SQ_F;
        const float* K = sK + cur * ATTN_SK_F;
#pragma unroll
        for (int k = 0; k < 16; k++) {
            ulonglong2 u0 = *(const ulonglong2*)(K + k * 132 + tn);
            ulonglong2 u1 = *(const ulonglong2*)(K + k * 132 + tn + 4);
            unsigned long long b2[4] = {u0.x, u0.y, u1.x, u1.y};
            unsigned long long a2[8];
#pragma unroll
            for (int i = 0; i < 8; i++) a2[i] = dup2(Q[(tm + i) * 17 + k]);
#pragma unroll
            for (int i = 0; i < 8; i++)
#pragma unroll
                for (int p = 0; p < 4; p++) ffma2(acc[i][p], a2[i], b2[p]);
        }
        if (it < 15) { storeQK(cur ^ 1); __syncthreads(); }
    }
    __syncthreads();   // all threads done reading sK before V overwrites it

    // ---------------- Phase 2: bias + softmax (registers) --------------
    float bj[8];
    {
        float4 q0 = *(const float4*)(bias + tn);
        float4 q1 = *(const float4*)(bias + tn + 4);
        bj[0] = q0.x; bj[1] = q0.y; bj[2] = q0.z; bj[3] = q0.w;
        bj[4] = q1.x; bj[5] = q1.y; bj[6] = q1.z; bj[7] = q1.w;
    }
    float c[8][8];
#pragma unroll
    for (int i = 0; i < 8; i++)
#pragma unroll
        for (int p = 0; p < 4; p++) {
            float2 v = unpack2(acc[i][p]);
            c[i][2 * p]     = v.x + bj[2 * p];
            c[i][2 * p + 1] = v.y + bj[2 * p + 1];
        }

#pragma unroll
    for (int i = 0; i < 8; i++) {
        float m = c[i][0];
#pragma unroll
        for (int j = 1; j < 8; j++) m = fmaxf(m, c[i][j]);
#pragma unroll
        for (int off = 1; off < 16; off <<= 1)
            m = fmaxf(m, __shfl_xor_sync(0xffffffffu, m, off, 16));
        float s = 0.f;
#pragma unroll
        for (int j = 0; j < 8; j++) { c[i][j] = __expf(c[i][j] - m); s += c[i][j]; }
#pragma unroll
        for (int off = 1; off < 16; off <<= 1)
            s += __shfl_xor_sync(0xffffffffu, s, off, 16);
        float inv = 1.0f / s;
#pragma unroll
        for (int j = 0; j < 8; j++) c[i][j] *= inv;
    }

    // write A (global) and stage into sA for phase 3
#pragma unroll
    for (int i = 0; i < 8; i++) {
        int t = tm + i;
        float4 v0 = make_float4(c[i][0], c[i][1], c[i][2], c[i][3]);
        float4 v1 = make_float4(c[i][4], c[i][5], c[i][6], c[i][7]);
        if (writeA) {
            float* dst = outA + ((size_t)bn * TT + t) * TT + tn;
            *(float4*)dst       = v0;
            *(float4*)(dst + 4) = v1;
        }
        *(float4*)(sA + t * 128 + tn)     = v0;
        *(float4*)(sA + t * 128 + tn + 4) = v1;
    }

    // ---------------- Phase 3: O = A @ V (flattened, double-buffered) ---
    float* sV = sK;   // alias (sK region is free now)

    auto loadV = [&](int tt) {
        int hb = tt >> 3, sc = tt & 7;
        const float* p = Vbase + (size_t)(sc * 16 + kkV) * HH + hb * 128 + j4V;
        a0 = *(const float4*)p;
        a1 = *(const float4*)(p + 8 * HH);
    };
    auto storeV = [&](int buf) {
        float* V = sV + buf * ATTN_SK_F;
        *(float4*)&V[kkV * 132 + j4V]       = a0;
        *(float4*)&V[(kkV + 8) * 132 + j4V] = a1;
    };

    loadV(0);
    storeV(0);
    __syncthreads();   // covers sA stores + V tile 0

#pragma unroll 1
    for (int tt = 0; tt < 16; ++tt) {
        const int cur = tt & 1;
        const int hb = tt >> 3, sc = tt & 7;
        if (sc == 0) {
#pragma unroll
            for (int i = 0; i < 8; i++)
#pragma unroll
                for (int p = 0; p < 4; p++) acc[i][p] = 0ull;
        }
        if (tt < 15) loadV(tt + 1);
        const float* V = sV + cur * ATTN_SK_F;
        const int s0 = sc * 16;
#pragma unroll
        for (int k = 0; k < 16; k++) {
            ulonglong2 u0 = *(const ulonglong2*)(V + k * 132 + tn);
            ulonglong2 u1 = *(const ulonglong2*)(V + k * 132 + tn + 4);
            unsigned long long b2[4] = {u0.x, u0.y, u1.x, u1.y};
            unsigned long long a2[8];
#pragma unroll
            for (int i = 0; i < 8; i++) a2[i] = dup2(sA[(tm + i) * 128 + s0 + k]);
#pragma unroll
            for (int i = 0; i < 8; i++)
#pragma unroll
                for (int p = 0; p < 4; p++) ffma2(acc[i][p], a2[i], b2[p]);
        }
        if (tt < 15) { storeV(cur ^ 1); __syncthreads(); }
        if (sc == 7) {
#pragma unroll
            for (int i = 0; i < 8; i++) {
                float2 p0 = unpack2(acc[i][0]);
                float2 p1 = unpack2(acc[i][1]);
                float2 p2 = unpack2(acc[i][2]);
                float2 p3 = unpack2(acc[i][3]);
                float4 v0 = make_float4(p0.x, p0.y, p1.x, p1.y);
                float4 v1 = make_float4(p2.x, p2.y, p3.x, p3.y);
                float* dst = outO + (size_t)bn * TT * HH
                           + (size_t)(tm + i) * HH + hb * 128 + tn;
                *(float4*)dst       = v0;
                *(float4*)(dst + 4) = v1;
            }
        }
    }
}

// =====================================================================
// Host launcher
// =====================================================================
extern "C" void kernel_launch(void* const* d_in, const int* in_sizes, int n_in,
                              void* d_out, int out_size)
{
    const float* node = nullptr;
    const float* neigh = nullptr;
    const float* bias = nullptr;
    const float* Ws[4] = {nullptr, nullptr, nullptr, nullptr};
    int wc = 0;
    for (int i = 0; i < n_in; i++) {
        int s = in_sizes[i];
        if      (s == BB * TT * HH)            node  = (const float*)d_in[i];
        else if (s == BB * NN * TT * HH)       neigh = (const float*)d_in[i];
        else if (s == TT)                      bias  = (const float*)d_in[i];
        else if (s == HH * HH && wc < 4)       Ws[wc++] = (const float*)d_in[i];
    }
    const float* Wq = Ws[0];
    const float* Wk = Ws[1];
    const float* Wv = Ws[2];
    const float* Wb = Ws[3];

    float *key, *val, *qw, *wqb;
    cudaGetSymbolAddress((void**)&key, g_key);
    cudaGetSymbolAddress((void**)&val, g_val);
    cudaGetSymbolAddress((void**)&qw,  g_qw);
    cudaGetSymbolAddress((void**)&wqb, g_wqb);

    cudaFuncSetAttribute(gemm128, cudaFuncAttributeMaxDynamicSharedMemorySize, GEMM_SMEM);
    cudaFuncSetAttribute(attn_kernel, cudaFuncAttributeMaxDynamicSharedMemorySize, SMEM_ATTN);

    // 1) Wqb = Wq^T @ Wb
    gemm128<<<dim3(2, 2), 256, GEMM_SMEM>>>(Wq, nullptr, Wb, wqb, 2, 0);
    // 2) qW = node @ Wqb
    gemm128<<<dim3(2, BB * TT / 128), 256, GEMM_SMEM>>>(node, nullptr, wqb, qw, 0, 0);
    // 3) key = kv @ Wk^T  (gathered rows)
    gemm128<<<dim3(2, BB * NP1 * TT / 128), 256, GEMM_SMEM>>>(node, neigh, Wk, key, 1, 1);
    // 4) value = kv @ Wv^T
    gemm128<<<dim3(2, BB * NP1 * TT / 128), 256, GEMM_SMEM>>>(node, neigh, Wv, val, 1, 1);

    // 5) fused attention
    const int O_elems = BB * NP1 * TT * HH;   // 35,651,584
    const int A_elems = BB * NP1 * TT * TT;   // 17,825,792
    int writeA = (out_size >= O_elems + A_elems) ? 1 : 0;
    float* outO = (float*)d_out;
    float* outA = outO + O_elems;

    attn_kernel<<<BB * NP1, 256, SMEM_ATTN>>>(qw, key, val, bias, outO, outA, writeA);
}